// round 14
// baseline (speedup 1.0000x reference)
#include <cuda_runtime.h>
#include <cuda_bf16.h>
#include <cstdint>

#define NN 50000
#define NE 600000
#define DD 128
#define NC 64
#define KW 36          // u32 words per 128-int8 k-row (144B padded) -> conflict-free

// ---------------- scratch (no allocations allowed) ----------------
__device__ float g_xw[NN * DD];
__device__ int   g_deg[NN];
__device__ float g_dinv[NN];
__device__ int   g_cluster_edges[NC];
__device__ int   g_intra_src[NE];
__device__ int   g_intra_dst[NE];
__device__ int   g_intra_count;
__device__ int   g_is_src[NN];
// W^T quantized: two int8 levels, padded [n][k] (KW words per row), + column scales
__device__ __align__(16) uint32_t g_wq1[DD * KW];
__device__ __align__(16) uint32_t g_wq2[DD * KW];
__device__ float g_invcw[DD];

__device__ __forceinline__ void imma16832(int c[4], const uint32_t a[4],
                                          uint32_t b0, uint32_t b1) {
    asm volatile(
        "mma.sync.aligned.m16n8k32.row.col.s32.s8.s8.s32 "
        "{%0,%1,%2,%3}, {%4,%5,%6,%7}, {%8,%9}, {%0,%1,%2,%3};"
        : "+r"(c[0]), "+r"(c[1]), "+r"(c[2]), "+r"(c[3])
        : "r"(a[0]), "r"(a[1]), "r"(a[2]), "r"(a[3]), "r"(b0), "r"(b1));
}
__device__ __forceinline__ uint32_t pack4(int a, int b, int c, int d) {
    return (uint32_t)(a & 255) | ((uint32_t)(b & 255) << 8) |
           ((uint32_t)(c & 255) << 16) | ((uint32_t)(d & 255) << 24);
}

// ---------------- kernel 1: zero counters ----------------
__global__ void zero_kernel() {
    int i = blockIdx.x * blockDim.x + threadIdx.x;
    if (i < NN) { g_deg[i] = 0; g_is_src[i] = 0; }
    if (i < NC) g_cluster_edges[i] = 0;
    if (i == 0) g_intra_count = 0;
}

// ---------------- kernel 2: quantize W columns to 2-level int8 ----------------
// block = column n (128 blocks), 128 threads = k. WT[n][k] = W[k][n].
__global__ void wprep_kernel(const float* __restrict__ W) {
    __shared__ float warpmax[4];
    __shared__ float s_ca;
    __shared__ signed char sq1[DD], sq2[DD];
    int n = blockIdx.x;
    int k = threadIdx.x;
    float v = W[k * DD + n];
    float m = fabsf(v);
    #pragma unroll
    for (int o = 16; o > 0; o >>= 1)
        m = fmaxf(m, __shfl_xor_sync(0xFFFFFFFFu, m, o));
    if ((k & 31) == 0) warpmax[k >> 5] = m;
    __syncthreads();
    if (k == 0) {
        float mm = fmaxf(fmaxf(warpmax[0], warpmax[1]),
                         fmaxf(warpmax[2], warpmax[3]));
        mm = fmaxf(mm, 1e-20f);
        s_ca = 127.0f / mm;
        g_invcw[n] = mm / 127.0f;
    }
    __syncthreads();
    float ca = s_ca;
    int q1 = __float2int_rn(v * ca);
    float r = v * ca - (float)q1;
    int q2 = __float2int_rn(r * 254.0f);
    sq1[k] = (signed char)q1;
    sq2[k] = (signed char)q2;
    __syncthreads();
    if (k < 32) {
        g_wq1[n * KW + k] = pack4(sq1[4*k], sq1[4*k+1], sq1[4*k+2], sq1[4*k+3]);
        g_wq2[n * KW + k] = pack4(sq2[4*k], sq2[4*k+1], sq2[4*k+2], sq2[4*k+3]);
    } else if (k < KW) {
        g_wq1[n * KW + k] = 0;
        g_wq2[n * KW + k] = 0;
    }
}

// ---------------- kernel 3: edge pass (mask + degree + warp-agg compact) ----
__global__ void edge_pass_kernel(const int* __restrict__ ei,
                                 const int* __restrict__ cl,
                                 int E) {
    int e = blockIdx.x * blockDim.x + threadIdx.x;
    int s = 0, d = 0, cs = 0;
    bool intra = false;
    if (e < E) {
        s = ei[e];
        d = ei[E + e];
        cs = cl[s];
        intra = (cs == cl[d]);
    }
    unsigned mask = __ballot_sync(0xFFFFFFFFu, intra);
    if (intra) {
        atomicAdd(&g_deg[d], 1);
        atomicAdd(&g_cluster_edges[cs], 1);
        g_is_src[s] = 1;
        int lane = threadIdx.x & 31;
        int leader = __ffs(mask) - 1;
        int base = 0;
        if (lane == leader) base = atomicAdd(&g_intra_count, __popc(mask));
        base = __shfl_sync(mask, base, leader);
        int pos = base + __popc(mask & ((1u << lane) - 1u));
        g_intra_src[pos] = s;
        g_intra_dst[pos] = d;
    }
}

// ---------------- kernel 4: fused IMMA GEMM + node epilogue ----------------
// 256 threads (8 warps), CTA tile M=64 x N=128, warp grid 2(M) x 4(N),
// warp tile 32x32. int8 2-level: acc_hi = q1a*q1w; acc_mid = q1a*q2w + q2a*q1w.
// out = invA*invW*(hi + mid/254). All fragment LDS conflict-free (KW=36 pad).
#define SM_INVA 0                    // 64 f
#define SM_INVW 256                  // 128 f
#define SM_BIAS 768                  // 128 f
#define SM_AQ1  1280                 // 64*KW u32 = 9216 B
#define SM_AQ2  (1280 + 9216)
#define SM_WQ1  (1280 + 2 * 9216)
#define SM_WQ2  (1280 + 2 * 9216 + DD * KW * 4)
#define SM_TOT  (1280 + 2 * 9216 + 2 * DD * KW * 4)   // 56576 B

__global__ void __launch_bounds__(256, 2)
gemm_fused_kernel(const float* __restrict__ X,
                  const float* __restrict__ b,
                  const int* __restrict__ cl,
                  float* __restrict__ out,
                  int n) {
    extern __shared__ char smem[];
    float* sInvA = (float*)(smem + SM_INVA);
    float* sInvW = (float*)(smem + SM_INVW);
    float* bias  = (float*)(smem + SM_BIAS);
    uint32_t* Aq1 = (uint32_t*)(smem + SM_AQ1);
    uint32_t* Aq2 = (uint32_t*)(smem + SM_AQ2);
    uint32_t* Wq1 = (uint32_t*)(smem + SM_WQ1);
    uint32_t* Wq2 = (uint32_t*)(smem + SM_WQ2);

    const int tid  = threadIdx.x;
    const int row0 = blockIdx.x * 64;

    if (tid < 128) { bias[tid] = b[tid]; sInvW[tid] = g_invcw[tid]; }

    // copy quantized W images (4608 u32 = 1152 uint4 each)
    {
        const uint4* g1 = (const uint4*)g_wq1;
        const uint4* g2 = (const uint4*)g_wq2;
        uint4* s1 = (uint4*)Wq1;
        uint4* s2 = (uint4*)Wq2;
        #pragma unroll
        for (int i = tid; i < 1152; i += 256) { s1[i] = g1[i]; s2[i] = g2[i]; }
    }

    // load X tile (64 rows), rowwise max (16 threads/row), quantize 2-level
    {
        const float4* X4 = (const float4*)X;
        #pragma unroll
        for (int i = tid; i < 64 * 16; i += 256) {
            int row = i >> 4;      // 0..63, constant across the 16-lane segment
            int c   = i & 15;      // 8-float chunk along k
            int grow = row0 + row;
            float4 a = make_float4(0.f, 0.f, 0.f, 0.f), a2 = a;
            if (grow < n) {
                a  = X4[grow * 32 + c * 2];
                a2 = X4[grow * 32 + c * 2 + 1];
            }
            float v[8] = {a.x, a.y, a.z, a.w, a2.x, a2.y, a2.z, a2.w};
            float m = 0.f;
            #pragma unroll
            for (int j = 0; j < 8; j++) m = fmaxf(m, fabsf(v[j]));
            #pragma unroll
            for (int o = 8; o > 0; o >>= 1)
                m = fmaxf(m, __shfl_xor_sync(0xFFFFFFFFu, m, o, 16));
            m = fmaxf(m, 1e-20f);
            float ca = 127.0f / m;
            if (c == 0) sInvA[row] = m / 127.0f;
            int q1[8], q2[8];
            #pragma unroll
            for (int j = 0; j < 8; j++) {
                q1[j] = __float2int_rn(v[j] * ca);
                float r = v[j] * ca - (float)q1[j];
                q2[j] = __float2int_rn(r * 254.0f);
            }
            Aq1[row * KW + c * 2]     = pack4(q1[0], q1[1], q1[2], q1[3]);
            Aq1[row * KW + c * 2 + 1] = pack4(q1[4], q1[5], q1[6], q1[7]);
            Aq2[row * KW + c * 2]     = pack4(q2[0], q2[1], q2[2], q2[3]);
            Aq2[row * KW + c * 2 + 1] = pack4(q2[4], q2[5], q2[6], q2[7]);
        }
    }
    __syncthreads();

    const int wid  = tid >> 5;
    const int lane = tid & 31;
    const int mw   = wid >> 2;    // 0..1 -> M offset mw*32
    const int nwp  = wid & 3;     // 0..3 -> N offset nwp*32
    const int g    = lane >> 2;   // 0..7
    const int tg   = lane & 3;    // 0..3

    int hi[2][4][4], mid[2][4][4];
    #pragma unroll
    for (int mt = 0; mt < 2; mt++)
        #pragma unroll
        for (int nt = 0; nt < 4; nt++)
            #pragma unroll
            for (int j = 0; j < 4; j++) { hi[mt][nt][j] = 0; mid[mt][nt][j] = 0; }

    // fragment word offsets: a: [row*KW + ks*8 + tg] (+4 for k+16), rows r, r+8
    const int ar0 = (mw * 32 + g) * KW + tg;         // mt=0 row
    const int ar1 = ar0 + 16 * KW;                   // mt=1 row
    const int bw0 = (nwp * 32 + g) * KW + tg;        // nt=0 col

    #pragma unroll
    for (int ks = 0; ks < 4; ks++) {
        const int ko = ks * 8;
        uint32_t aq1[2][4], aq2[2][4];
        #pragma unroll
        for (int mt = 0; mt < 2; mt++) {
            int base = (mt ? ar1 : ar0) + ko;
            aq1[mt][0] = Aq1[base];
            aq1[mt][1] = Aq1[base + 8 * KW];
            aq1[mt][2] = Aq1[base + 4];
            aq1[mt][3] = Aq1[base + 8 * KW + 4];
            aq2[mt][0] = Aq2[base];
            aq2[mt][1] = Aq2[base + 8 * KW];
            aq2[mt][2] = Aq2[base + 4];
            aq2[mt][3] = Aq2[base + 8 * KW + 4];
        }
        #pragma unroll
        for (int nt = 0; nt < 4; nt++) {
            int bb = bw0 + nt * 8 * KW + ko;
            uint32_t b1a = Wq1[bb], b1b = Wq1[bb + 4];
            uint32_t b2a = Wq2[bb], b2b = Wq2[bb + 4];
            imma16832(hi[0][nt],  aq1[0], b1a, b1b);
            imma16832(hi[1][nt],  aq1[1], b1a, b1b);
            imma16832(mid[0][nt], aq1[0], b2a, b2b);
            imma16832(mid[1][nt], aq1[1], b2a, b2b);
            imma16832(mid[0][nt], aq2[0], b1a, b1b);
            imma16832(mid[1][nt], aq2[1], b1a, b1b);
        }
    }

    // dinv for this CTA's rows
    if (tid < 64) {
        int row = row0 + tid;
        if (row < n) g_dinv[row] = rsqrtf((float)g_deg[row] + 1.0f);
    }

    // fused dequant + node epilogue
    const float INV254 = 1.0f / 254.0f;
    #pragma unroll
    for (int mt = 0; mt < 2; mt++) {
        #pragma unroll
        for (int half = 0; half < 2; half++) {
            int rl  = mw * 32 + mt * 16 + g + half * 8;
            int row = row0 + rl;
            if (row >= n) continue;
            float invA = sInvA[rl];
            float deg = (float)g_deg[row] + 1.0f;
            float inv = 1.0f / deg;
            bool  has = (g_cluster_edges[cl[row]] > 0);
            bool  src = (g_is_src[row] != 0);
            #pragma unroll
            for (int nt = 0; nt < 4; nt++) {
                int ncol = nwp * 32 + nt * 8 + tg * 2;
                float vx = ((float)hi[mt][nt][half*2]   +
                            (float)mid[mt][nt][half*2]   * INV254) * invA * sInvW[ncol];
                float vy = ((float)hi[mt][nt][half*2+1] +
                            (float)mid[mt][nt][half*2+1] * INV254) * invA * sInvW[ncol+1];
                if (src) *(float2*)(g_xw + row * DD + ncol) = make_float2(vx, vy);
                float2 o;
                if (has) {
                    o.x = fmaf(vx, inv, bias[ncol]);
                    o.y = fmaf(vy, inv, bias[ncol + 1]);
                } else {
                    o = *(const float2*)(X + row * DD + ncol);
                }
                *(float2*)(out + row * DD + ncol) = o;
            }
        }
    }
}

// ---------------- kernel 5: scatter over compacted intra edges --------------
__global__ void scatter_kernel(float* __restrict__ out) {
    int cnt  = g_intra_count;
    int gtid = blockIdx.x * blockDim.x + threadIdx.x;
    int warp = gtid >> 5;
    int lane = gtid & 31;
    int nw   = (gridDim.x * blockDim.x) >> 5;

    for (int e = warp; e < cnt; e += nw) {
        int s = g_intra_src[e];
        int d = g_intra_dst[e];
        float w = g_dinv[s] * g_dinv[d];
        float4 v = ((const float4*)(g_xw + s * DD))[lane];
        float* o = out + d * DD + lane * 4;
        atomicAdd(o + 0, w * v.x);
        atomicAdd(o + 1, w * v.y);
        atomicAdd(o + 2, w * v.z);
        atomicAdd(o + 3, w * v.w);
    }
}

// ---------------- launch ----------------
extern "C" void kernel_launch(void* const* d_in, const int* in_sizes, int n_in,
                              void* d_out, int out_size) {
    const float* X  = (const float*)d_in[0];
    const float* W  = (const float*)d_in[1];
    const float* b  = (const float*)d_in[2];
    // d_in[3] = edge_attr (unused)
    const int* cl = (const int*)d_in[4];
    const int* ei = (const int*)d_in[5];
    float* out = (float*)d_out;

    const int N = in_sizes[4];
    const int E = in_sizes[3];

    cudaFuncSetAttribute(gemm_fused_kernel,
                         cudaFuncAttributeMaxDynamicSharedMemorySize, SM_TOT);

    zero_kernel<<<(NN + 255) / 256, 256>>>();
    wprep_kernel<<<DD, DD>>>(W);
    edge_pass_kernel<<<(E + 255) / 256, 256>>>(ei, cl, E);
    gemm_fused_kernel<<<(N + 63) / 64, 256, SM_TOT>>>(X, b, cl, out, N);
    scatter_kernel<<<512, 256>>>(out);
}

// round 15
// speedup vs baseline: 1.6824x; 1.6824x over previous
#include <cuda_runtime.h>
#include <cuda_fp16.h>
#include <cstdint>

#define NN 50000
#define NE 600000
#define DD 128
#define NC 64
#define SWIDE 136   // padded row stride in fp16 elems (272B) -> conflict-free ldmatrix

// ---------------- scratch (no allocations allowed) ----------------
__device__ float g_xw[NN * DD];
__device__ int   g_deg[NN];
__device__ float g_dinv[NN];
__device__ int   g_cluster_edges[NC];
__device__ int   g_intra_src[NE];
__device__ int   g_intra_dst[NE];
__device__ int   g_intra_count;
__device__ int   g_is_src[NN];
// W^T fp16, padded row-major [n][k] (row stride SWIDE)
__device__ __align__(16) __half g_wt[DD * SWIDE];

__device__ __forceinline__ uint32_t packh2(__half a, __half b) {
    __half2 t = __halves2half2(a, b);
    return *reinterpret_cast<uint32_t*>(&t);
}
__device__ __forceinline__ void mma16816(float c[4], const uint32_t a[4],
                                         uint32_t b0, uint32_t b1) {
    asm volatile(
        "mma.sync.aligned.m16n8k16.row.col.f32.f16.f16.f32 "
        "{%0,%1,%2,%3}, {%4,%5,%6,%7}, {%8,%9}, {%0,%1,%2,%3};"
        : "+f"(c[0]), "+f"(c[1]), "+f"(c[2]), "+f"(c[3])
        : "r"(a[0]), "r"(a[1]), "r"(a[2]), "r"(a[3]), "r"(b0), "r"(b1));
}
__device__ __forceinline__ void ldsm_x4(uint32_t r[4], uint32_t saddr) {
    asm volatile(
        "ldmatrix.sync.aligned.m8n8.x4.shared.b16 {%0,%1,%2,%3}, [%4];"
        : "=r"(r[0]), "=r"(r[1]), "=r"(r[2]), "=r"(r[3]) : "r"(saddr));
}
__device__ __forceinline__ uint32_t smem_to_u32(const void* p) {
    uint32_t a;
    asm("{ .reg .u64 t; cvta.to.shared.u64 t, %1; cvt.u32.u64 %0, t; }"
        : "=r"(a) : "l"(p));
    return a;
}
__device__ __forceinline__ void cp_async16(uint32_t saddr, const void* gptr) {
    asm volatile("cp.async.cg.shared.global [%0], [%1], 16;"
                 :: "r"(saddr), "l"(gptr));
}

// ---------------- kernel 1: zero counters ----------------
__global__ void zero_kernel() {
    int i = blockIdx.x * blockDim.x + threadIdx.x;
    if (i < NN) { g_deg[i] = 0; g_is_src[i] = 0; }
    if (i < NC) g_cluster_edges[i] = 0;
    if (i == 0) g_intra_count = 0;
}

// ---------------- kernel 2: W^T fp16, padded row-major ----------------
__global__ void wprep_kernel(const float* __restrict__ W) {
    int i = blockIdx.x * blockDim.x + threadIdx.x;
    if (i >= DD * SWIDE) return;
    int nrow = i / SWIDE;
    int k    = i % SWIDE;
    g_wt[i] = (k < DD) ? __float2half_rn(W[k * DD + nrow]) : __float2half_rn(0.f);
}

// ---------------- kernel 3: edge pass (mask + degree + warp-agg compact) ----
__global__ void edge_pass_kernel(const int* __restrict__ ei,
                                 const int* __restrict__ cl,
                                 int E) {
    int e = blockIdx.x * blockDim.x + threadIdx.x;
    int s = 0, d = 0, cs = 0;
    bool intra = false;
    if (e < E) {
        s = ei[e];
        d = ei[E + e];
        cs = cl[s];
        intra = (cs == cl[d]);
    }
    unsigned mask = __ballot_sync(0xFFFFFFFFu, intra);
    if (intra) {
        atomicAdd(&g_deg[d], 1);
        atomicAdd(&g_cluster_edges[cs], 1);
        g_is_src[s] = 1;
        int lane = threadIdx.x & 31;
        int leader = __ffs(mask) - 1;
        int base = 0;
        if (lane == leader) base = atomicAdd(&g_intra_count, __popc(mask));
        base = __shfl_sync(mask, base, leader);
        int pos = base + __popc(mask & ((1u << lane) - 1u));
        g_intra_src[pos] = s;
        g_intra_dst[pos] = d;
    }
}

// ---------------- kernel 4: fused fp16 2-term HMMA GEMM + node epilogue -----
// 256 threads (8 warps), CTA tile M=64 x N=128, 2 CTAs/SM.
// D = Ahi*W + Alo*W (fp16 split of A, single fp16 W), fp32 accum.
// Warp grid 2(M) x 4(N), warp tile 32x32. All fragments via ldmatrix.
#define ATILE (64 * SWIDE * 2)          // 17408 B
#define WTILE (DD * SWIDE * 2)          // 34816 B
#define SM_B    0
#define SM_AHI  512
#define SM_ALO  (512 + ATILE)
#define SM_W    (512 + 2 * ATILE)
#define SM_TOT  (512 + 2 * ATILE + WTILE)   // 70144 B -> 2 CTAs/SM

__global__ void __launch_bounds__(256, 2)
gemm_fused_kernel(const float* __restrict__ X,
                  const float* __restrict__ b,
                  const int* __restrict__ cl,
                  float* __restrict__ out,
                  int n) {
    extern __shared__ char smem[];
    float* bias = (float*)(smem + SM_B);
    __half* Ahi = (__half*)(smem + SM_AHI);
    __half* Alo = (__half*)(smem + SM_ALO);

    const int tid  = threadIdx.x;
    const int row0 = blockIdx.x * 64;
    const uint32_t sbase = smem_to_u32(smem);

    // async W copy (34816B = 2176 uint4) overlapping the X prologue
    {
        const uint4* gw = (const uint4*)g_wt;
        #pragma unroll
        for (int i = tid; i < 2176; i += 256)
            cp_async16(sbase + SM_W + i * 16, gw + i);
        asm volatile("cp.async.commit_group;");
    }

    if (tid < 128) bias[tid] = b[tid];

    // load X tile (64 rows), fp16 split, store padded
    {
        const float4* X4 = (const float4*)X;
        #pragma unroll
        for (int i = tid; i < 64 * 16; i += 256) {
            int row = i >> 4;
            int c   = i & 15;
            int grow = row0 + row;
            float4 a = make_float4(0.f, 0.f, 0.f, 0.f), a2 = a;
            if (grow < n) {
                a  = X4[grow * 32 + c * 2];
                a2 = X4[grow * 32 + c * 2 + 1];
            }
            float v[8] = {a.x, a.y, a.z, a.w, a2.x, a2.y, a2.z, a2.w};
            uint32_t hi[4], lo[4];
            #pragma unroll
            for (int j = 0; j < 4; j++) {
                __half h0 = __float2half_rn(v[2 * j]);
                __half h1 = __float2half_rn(v[2 * j + 1]);
                __half l0 = __float2half_rn(v[2 * j]     - __half2float(h0));
                __half l1 = __float2half_rn(v[2 * j + 1] - __half2float(h1));
                hi[j] = packh2(h0, h1);
                lo[j] = packh2(l0, l1);
            }
            *(uint4*)(Ahi + row * SWIDE + c * 8) = make_uint4(hi[0], hi[1], hi[2], hi[3]);
            *(uint4*)(Alo + row * SWIDE + c * 8) = make_uint4(lo[0], lo[1], lo[2], lo[3]);
        }
    }
    asm volatile("cp.async.wait_group 0;" ::: "memory");
    __syncthreads();

    const int wid  = tid >> 5;
    const int lane = tid & 31;
    const int mw   = wid >> 2;    // 0..1 -> M offset mw*32
    const int nwp  = wid & 3;     // 0..3 -> N offset nwp*32
    const int g    = lane >> 2;   // 0..7
    const int tg   = lane & 3;    // 0..3

    const uint32_t aoff =
        ((uint32_t)(mw * 32 + (lane & 15)) * SWIDE + (uint32_t)(lane >> 4) * 8) * 2;
    const uint32_t boff =
        ((uint32_t)(nwp * 32 + ((lane >> 4) & 1) * 8 + (lane & 7)) * SWIDE
         + (uint32_t)((lane >> 3) & 1) * 8) * 2;
    const uint32_t AhiB = sbase + SM_AHI + aoff;
    const uint32_t AloB = sbase + SM_ALO + aoff;
    const uint32_t WB   = sbase + SM_W + boff;
    const uint32_t STEP16 = 16u * SWIDE * 2u;

    float acc[2][4][4];
    #pragma unroll
    for (int mt = 0; mt < 2; mt++)
        #pragma unroll
        for (int nt = 0; nt < 4; nt++)
            #pragma unroll
            for (int j = 0; j < 4; j++) acc[mt][nt][j] = 0.f;

    // software-pipelined mainloop: prefetch ks+1 fragments behind 16 MMAs
    uint32_t b01[4], b23[4], ah0[4], ah1[4], al0[4], al1[4];
    ldsm_x4(b01, WB);
    ldsm_x4(b23, WB + STEP16);
    ldsm_x4(ah0, AhiB);
    ldsm_x4(ah1, AhiB + STEP16);
    ldsm_x4(al0, AloB);
    ldsm_x4(al1, AloB + STEP16);
    #pragma unroll
    for (int ks = 0; ks < 8; ks++) {
        uint32_t nb01[4], nb23[4], nah0[4], nah1[4], nal0[4], nal1[4];
        if (ks < 7) {
            const uint32_t ko = (uint32_t)(ks + 1) * 32u;
            ldsm_x4(nb01, WB + ko);
            ldsm_x4(nb23, WB + ko + STEP16);
            ldsm_x4(nah0, AhiB + ko);
            ldsm_x4(nah1, AhiB + ko + STEP16);
            ldsm_x4(nal0, AloB + ko);
            ldsm_x4(nal1, AloB + ko + STEP16);
        }
        mma16816(acc[0][0], ah0, b01[0], b01[1]);
        mma16816(acc[0][1], ah0, b01[2], b01[3]);
        mma16816(acc[0][2], ah0, b23[0], b23[1]);
        mma16816(acc[0][3], ah0, b23[2], b23[3]);
        mma16816(acc[1][0], ah1, b01[0], b01[1]);
        mma16816(acc[1][1], ah1, b01[2], b01[3]);
        mma16816(acc[1][2], ah1, b23[0], b23[1]);
        mma16816(acc[1][3], ah1, b23[2], b23[3]);
        mma16816(acc[0][0], al0, b01[0], b01[1]);
        mma16816(acc[0][1], al0, b01[2], b01[3]);
        mma16816(acc[0][2], al0, b23[0], b23[1]);
        mma16816(acc[0][3], al0, b23[2], b23[3]);
        mma16816(acc[1][0], al1, b01[0], b01[1]);
        mma16816(acc[1][1], al1, b01[2], b01[3]);
        mma16816(acc[1][2], al1, b23[0], b23[1]);
        mma16816(acc[1][3], al1, b23[2], b23[3]);
        if (ks < 7) {
            #pragma unroll
            for (int j = 0; j < 4; j++) {
                b01[j] = nb01[j]; b23[j] = nb23[j];
                ah0[j] = nah0[j]; ah1[j] = nah1[j];
                al0[j] = nal0[j]; al1[j] = nal1[j];
            }
        }
    }

    // dinv for this CTA's rows
    if (tid < 64) {
        int row = row0 + tid;
        if (row < n) g_dinv[row] = rsqrtf((float)g_deg[row] + 1.0f);
    }

    // fused node epilogue
    #pragma unroll
    for (int mt = 0; mt < 2; mt++) {
        #pragma unroll
        for (int half = 0; half < 2; half++) {
            int row = row0 + mw * 32 + mt * 16 + g + half * 8;
            if (row >= n) continue;
            float deg = (float)g_deg[row] + 1.0f;
            float inv = 1.0f / deg;
            bool  has = (g_cluster_edges[cl[row]] > 0);
            bool  src = (g_is_src[row] != 0);
            #pragma unroll
            for (int nt = 0; nt < 4; nt++) {
                int ncol = nwp * 32 + nt * 8 + tg * 2;
                float2 v = make_float2(acc[mt][nt][half * 2],
                                       acc[mt][nt][half * 2 + 1]);
                if (src) *(float2*)(g_xw + row * DD + ncol) = v;
                float2 o;
                if (has) {
                    o.x = fmaf(v.x, inv, bias[ncol]);
                    o.y = fmaf(v.y, inv, bias[ncol + 1]);
                } else {
                    o = *(const float2*)(X + row * DD + ncol);
                }
                *(float2*)(out + row * DD + ncol) = o;
            }
        }
    }
}

// ---------------- kernel 5: scatter over compacted intra edges --------------
__global__ void scatter_kernel(float* __restrict__ out) {
    int cnt  = g_intra_count;
    int gtid = blockIdx.x * blockDim.x + threadIdx.x;
    int warp = gtid >> 5;
    int lane = gtid & 31;
    int nw   = (gridDim.x * blockDim.x) >> 5;

    for (int e = warp; e < cnt; e += nw) {
        int s = g_intra_src[e];
        int d = g_intra_dst[e];
        float w = g_dinv[s] * g_dinv[d];
        float4 v = ((const float4*)(g_xw + s * DD))[lane];
        float* o = out + d * DD + lane * 4;
        atomicAdd(o + 0, w * v.x);
        atomicAdd(o + 1, w * v.y);
        atomicAdd(o + 2, w * v.z);
        atomicAdd(o + 3, w * v.w);
    }
}

// ---------------- launch ----------------
extern "C" void kernel_launch(void* const* d_in, const int* in_sizes, int n_in,
                              void* d_out, int out_size) {
    const float* X  = (const float*)d_in[0];
    const float* W  = (const float*)d_in[1];
    const float* b  = (const float*)d_in[2];
    // d_in[3] = edge_attr (unused)
    const int* cl = (const int*)d_in[4];
    const int* ei = (const int*)d_in[5];
    float* out = (float*)d_out;

    const int N = in_sizes[4];
    const int E = in_sizes[3];

    cudaFuncSetAttribute(gemm_fused_kernel,
                         cudaFuncAttributeMaxDynamicSharedMemorySize, SM_TOT);

    zero_kernel<<<(NN + 255) / 256, 256>>>();
    wprep_kernel<<<(DD * SWIDE + 255) / 256, 256>>>(W);
    edge_pass_kernel<<<(E + 255) / 256, 256>>>(ei, cl, E);
    gemm_fused_kernel<<<(N + 63) / 64, 256, SM_TOT>>>(X, b, cl, out, N);
    scatter_kernel<<<512, 256>>>(out);
}

// round 16
// speedup vs baseline: 1.7746x; 1.0548x over previous
#include <cuda_runtime.h>
#include <cuda_fp16.h>
#include <cstdint>

#define NN 50000
#define NE 600000
#define DD 128
#define NC 64
#define SWIDE 136   // padded row stride in fp16 elems (272B) -> conflict-free ldmatrix

// ---------------- scratch (no allocations allowed) ----------------
// NOTE: counters (g_deg, g_is_src, g_cluster_edges, g_intra_count) are
// zero-initialized at module load and re-zeroed at the END of scatter_kernel,
// so every kernel_launch call sees them zeroed (replay-invariant).
__device__ float g_xw[NN * DD];
__device__ int   g_deg[NN];
__device__ float g_dinv[NN];
__device__ int   g_cluster_edges[NC];
__device__ int   g_intra_src[NE];
__device__ int   g_intra_dst[NE];
__device__ int   g_intra_count;
__device__ int   g_scatter_cnt;     // snapshot taken by gemm (block 0)
__device__ int   g_is_src[NN];
// W^T fp16, padded row-major [n][k] (row stride SWIDE)
__device__ __align__(16) __half g_wt[DD * SWIDE];

__device__ __forceinline__ uint32_t packh2(__half a, __half b) {
    __half2 t = __halves2half2(a, b);
    return *reinterpret_cast<uint32_t*>(&t);
}
__device__ __forceinline__ void mma16816(float c[4], const uint32_t a[4],
                                         uint32_t b0, uint32_t b1) {
    asm volatile(
        "mma.sync.aligned.m16n8k16.row.col.f32.f16.f16.f32 "
        "{%0,%1,%2,%3}, {%4,%5,%6,%7}, {%8,%9}, {%0,%1,%2,%3};"
        : "+f"(c[0]), "+f"(c[1]), "+f"(c[2]), "+f"(c[3])
        : "r"(a[0]), "r"(a[1]), "r"(a[2]), "r"(a[3]), "r"(b0), "r"(b1));
}
__device__ __forceinline__ void ldsm_x4(uint32_t r[4], uint32_t saddr) {
    asm volatile(
        "ldmatrix.sync.aligned.m8n8.x4.shared.b16 {%0,%1,%2,%3}, [%4];"
        : "=r"(r[0]), "=r"(r[1]), "=r"(r[2]), "=r"(r[3]) : "r"(saddr));
}
__device__ __forceinline__ uint32_t smem_to_u32(const void* p) {
    uint32_t a;
    asm("{ .reg .u64 t; cvta.to.shared.u64 t, %1; cvt.u32.u64 %0, t; }"
        : "=r"(a) : "l"(p));
    return a;
}
__device__ __forceinline__ void cp_async16(uint32_t saddr, const void* gptr) {
    asm volatile("cp.async.cg.shared.global [%0], [%1], 16;"
                 :: "r"(saddr), "l"(gptr));
}

// ---------------- kernel 1: edge pass + W prep (fused) ----------------------
// blocks [0, edge_blocks): edge mask + degree + warp-agg compaction
// blocks [edge_blocks, edge_blocks+68): elementwise W^T fp16 conversion
__global__ void edge_wprep_kernel(const int* __restrict__ ei,
                                  const int* __restrict__ cl,
                                  const float* __restrict__ W,
                                  int E, int edge_blocks) {
    if ((int)blockIdx.x >= edge_blocks) {
        int i = ((int)blockIdx.x - edge_blocks) * 256 + threadIdx.x;
        if (i < DD * SWIDE) {
            int nrow = i / SWIDE;
            int k    = i % SWIDE;
            g_wt[i] = (k < DD) ? __float2half_rn(W[k * DD + nrow])
                               : __float2half_rn(0.f);
        }
        return;
    }
    int e = blockIdx.x * blockDim.x + threadIdx.x;
    int s = 0, d = 0, cs = 0;
    bool intra = false;
    if (e < E) {
        s = ei[e];
        d = ei[E + e];
        cs = cl[s];
        intra = (cs == cl[d]);
    }
    unsigned mask = __ballot_sync(0xFFFFFFFFu, intra);
    if (intra) {
        atomicAdd(&g_deg[d], 1);
        atomicAdd(&g_cluster_edges[cs], 1);
        g_is_src[s] = 1;
        int lane = threadIdx.x & 31;
        int leader = __ffs(mask) - 1;
        int base = 0;
        if (lane == leader) base = atomicAdd(&g_intra_count, __popc(mask));
        base = __shfl_sync(mask, base, leader);
        int pos = base + __popc(mask & ((1u << lane) - 1u));
        g_intra_src[pos] = s;
        g_intra_dst[pos] = d;
    }
}

// ---------------- kernel 2: fused fp16 2-term HMMA GEMM + node epilogue -----
// 256 threads (8 warps), CTA tile M=64 x N=128, 2 CTAs/SM.
// D = Ahi*W + Alo*W (fp16 split of A, single fp16 W), fp32 accum.
#define ATILE (64 * SWIDE * 2)          // 17408 B
#define WTILE (DD * SWIDE * 2)          // 34816 B
#define SM_B    0
#define SM_AHI  512
#define SM_ALO  (512 + ATILE)
#define SM_W    (512 + 2 * ATILE)
#define SM_TOT  (512 + 2 * ATILE + WTILE)   // 70144 B -> 2 CTAs/SM

__global__ void __launch_bounds__(256, 2)
gemm_fused_kernel(const float* __restrict__ X,
                  const float* __restrict__ b,
                  const int* __restrict__ cl,
                  float* __restrict__ out,
                  int n) {
    extern __shared__ char smem[];
    float* bias = (float*)(smem + SM_B);
    __half* Ahi = (__half*)(smem + SM_AHI);
    __half* Alo = (__half*)(smem + SM_ALO);

    const int tid  = threadIdx.x;
    const int row0 = blockIdx.x * 64;
    const uint32_t sbase = smem_to_u32(smem);

    // snapshot intra count so scatter can read it while cleanup zeroes the live one
    if (blockIdx.x == 0 && tid == 0) g_scatter_cnt = g_intra_count;

    // async W copy (34816B = 2176 uint4) overlapping the X prologue
    {
        const uint4* gw = (const uint4*)g_wt;
        #pragma unroll
        for (int i = tid; i < 2176; i += 256)
            cp_async16(sbase + SM_W + i * 16, gw + i);
        asm volatile("cp.async.commit_group;");
    }

    if (tid < 128) bias[tid] = b[tid];

    // load X tile (64 rows), fp16 split, store padded
    {
        const float4* X4 = (const float4*)X;
        #pragma unroll
        for (int i = tid; i < 64 * 16; i += 256) {
            int row = i >> 4;
            int c   = i & 15;
            int grow = row0 + row;
            float4 a = make_float4(0.f, 0.f, 0.f, 0.f), a2 = a;
            if (grow < n) {
                a  = X4[grow * 32 + c * 2];
                a2 = X4[grow * 32 + c * 2 + 1];
            }
            float v[8] = {a.x, a.y, a.z, a.w, a2.x, a2.y, a2.z, a2.w};
            uint32_t hi[4], lo[4];
            #pragma unroll
            for (int j = 0; j < 4; j++) {
                __half h0 = __float2half_rn(v[2 * j]);
                __half h1 = __float2half_rn(v[2 * j + 1]);
                __half l0 = __float2half_rn(v[2 * j]     - __half2float(h0));
                __half l1 = __float2half_rn(v[2 * j + 1] - __half2float(h1));
                hi[j] = packh2(h0, h1);
                lo[j] = packh2(l0, l1);
            }
            *(uint4*)(Ahi + row * SWIDE + c * 8) = make_uint4(hi[0], hi[1], hi[2], hi[3]);
            *(uint4*)(Alo + row * SWIDE + c * 8) = make_uint4(lo[0], lo[1], lo[2], lo[3]);
        }
    }
    asm volatile("cp.async.wait_group 0;" ::: "memory");
    __syncthreads();

    const int wid  = tid >> 5;
    const int lane = tid & 31;
    const int mw   = wid >> 2;    // 0..1 -> M offset mw*32
    const int nwp  = wid & 3;     // 0..3 -> N offset nwp*32
    const int g    = lane >> 2;   // 0..7
    const int tg   = lane & 3;    // 0..3

    const uint32_t aoff =
        ((uint32_t)(mw * 32 + (lane & 15)) * SWIDE + (uint32_t)(lane >> 4) * 8) * 2;
    const uint32_t boff =
        ((uint32_t)(nwp * 32 + ((lane >> 4) & 1) * 8 + (lane & 7)) * SWIDE
         + (uint32_t)((lane >> 3) & 1) * 8) * 2;
    const uint32_t AhiB = sbase + SM_AHI + aoff;
    const uint32_t AloB = sbase + SM_ALO + aoff;
    const uint32_t WB   = sbase + SM_W + boff;
    const uint32_t STEP16 = 16u * SWIDE * 2u;

    float acc[2][4][4];
    #pragma unroll
    for (int mt = 0; mt < 2; mt++)
        #pragma unroll
        for (int nt = 0; nt < 4; nt++)
            #pragma unroll
            for (int j = 0; j < 4; j++) acc[mt][nt][j] = 0.f;

    // software-pipelined mainloop: prefetch ks+1 fragments behind 16 MMAs
    uint32_t b01[4], b23[4], ah0[4], ah1[4], al0[4], al1[4];
    ldsm_x4(b01, WB);
    ldsm_x4(b23, WB + STEP16);
    ldsm_x4(ah0, AhiB);
    ldsm_x4(ah1, AhiB + STEP16);
    ldsm_x4(al0, AloB);
    ldsm_x4(al1, AloB + STEP16);
    #pragma unroll
    for (int ks = 0; ks < 8; ks++) {
        uint32_t nb01[4], nb23[4], nah0[4], nah1[4], nal0[4], nal1[4];
        if (ks < 7) {
            const uint32_t ko = (uint32_t)(ks + 1) * 32u;
            ldsm_x4(nb01, WB + ko);
            ldsm_x4(nb23, WB + ko + STEP16);
            ldsm_x4(nah0, AhiB + ko);
            ldsm_x4(nah1, AhiB + ko + STEP16);
            ldsm_x4(nal0, AloB + ko);
            ldsm_x4(nal1, AloB + ko + STEP16);
        }
        mma16816(acc[0][0], ah0, b01[0], b01[1]);
        mma16816(acc[0][1], ah0, b01[2], b01[3]);
        mma16816(acc[0][2], ah0, b23[0], b23[1]);
        mma16816(acc[0][3], ah0, b23[2], b23[3]);
        mma16816(acc[1][0], ah1, b01[0], b01[1]);
        mma16816(acc[1][1], ah1, b01[2], b01[3]);
        mma16816(acc[1][2], ah1, b23[0], b23[1]);
        mma16816(acc[1][3], ah1, b23[2], b23[3]);
        mma16816(acc[0][0], al0, b01[0], b01[1]);
        mma16816(acc[0][1], al0, b01[2], b01[3]);
        mma16816(acc[0][2], al0, b23[0], b23[1]);
        mma16816(acc[0][3], al0, b23[2], b23[3]);
        mma16816(acc[1][0], al1, b01[0], b01[1]);
        mma16816(acc[1][1], al1, b01[2], b01[3]);
        mma16816(acc[1][2], al1, b23[0], b23[1]);
        mma16816(acc[1][3], al1, b23[2], b23[3]);
        if (ks < 7) {
            #pragma unroll
            for (int j = 0; j < 4; j++) {
                b01[j] = nb01[j]; b23[j] = nb23[j];
                ah0[j] = nah0[j]; ah1[j] = nah1[j];
                al0[j] = nal0[j]; al1[j] = nal1[j];
            }
        }
    }

    // dinv for this CTA's rows
    if (tid < 64) {
        int row = row0 + tid;
        if (row < n) g_dinv[row] = rsqrtf((float)g_deg[row] + 1.0f);
    }

    // fused node epilogue
    #pragma unroll
    for (int mt = 0; mt < 2; mt++) {
        #pragma unroll
        for (int half = 0; half < 2; half++) {
            int row = row0 + mw * 32 + mt * 16 + g + half * 8;
            if (row >= n) continue;
            float deg = (float)g_deg[row] + 1.0f;
            float inv = 1.0f / deg;
            bool  has = (g_cluster_edges[cl[row]] > 0);
            bool  src = (g_is_src[row] != 0);
            #pragma unroll
            for (int nt = 0; nt < 4; nt++) {
                int ncol = nwp * 32 + nt * 8 + tg * 2;
                float2 v = make_float2(acc[mt][nt][half * 2],
                                       acc[mt][nt][half * 2 + 1]);
                if (src) *(float2*)(g_xw + row * DD + ncol) = v;
                float2 o;
                if (has) {
                    o.x = fmaf(v.x, inv, bias[ncol]);
                    o.y = fmaf(v.y, inv, bias[ncol + 1]);
                } else {
                    o = *(const float2*)(X + row * DD + ncol);
                }
                *(float2*)(out + row * DD + ncol) = o;
            }
        }
    }
}

// ---------------- kernel 3: scatter + counter cleanup for next replay -------
__global__ void scatter_kernel(float* __restrict__ out) {
    int cnt  = g_scatter_cnt;   // snapshot (live counter is zeroed below)
    int gtid = blockIdx.x * blockDim.x + threadIdx.x;
    int nthr = gridDim.x * blockDim.x;
    int warp = gtid >> 5;
    int lane = gtid & 31;
    int nw   = nthr >> 5;

    for (int e = warp; e < cnt; e += nw) {
        int s = g_intra_src[e];
        int d = g_intra_dst[e];
        float w = g_dinv[s] * g_dinv[d];
        float4 v = ((const float4*)(g_xw + s * DD))[lane];
        float* o = out + d * DD + lane * 4;
        atomicAdd(o + 0, w * v.x);
        atomicAdd(o + 1, w * v.y);
        atomicAdd(o + 2, w * v.z);
        atomicAdd(o + 3, w * v.w);
    }

    // cleanup: restore the zeroed-counter invariant for the next replay.
    // (g_deg/g_is_src/g_cluster_edges/g_intra_count are not read again this call.)
    for (int i = gtid; i < NN; i += nthr) { g_deg[i] = 0; g_is_src[i] = 0; }
    if (gtid < NC) g_cluster_edges[gtid] = 0;
    if (gtid == 0) g_intra_count = 0;
}

// ---------------- launch ----------------
extern "C" void kernel_launch(void* const* d_in, const int* in_sizes, int n_in,
                              void* d_out, int out_size) {
    const float* X  = (const float*)d_in[0];
    const float* W  = (const float*)d_in[1];
    const float* b  = (const float*)d_in[2];
    // d_in[3] = edge_attr (unused)
    const int* cl = (const int*)d_in[4];
    const int* ei = (const int*)d_in[5];
    float* out = (float*)d_out;

    const int N = in_sizes[4];
    const int E = in_sizes[3];

    cudaFuncSetAttribute(gemm_fused_kernel,
                         cudaFuncAttributeMaxDynamicSharedMemorySize, SM_TOT);

    const int edge_blocks  = (E + 255) / 256;
    const int wprep_blocks = (DD * SWIDE + 255) / 256;
    edge_wprep_kernel<<<edge_blocks + wprep_blocks, 256>>>(ei, cl, W, E, edge_blocks);
    gemm_fused_kernel<<<(N + 63) / 64, 256, SM_TOT>>>(X, b, cl, out, N);
    scatter_kernel<<<512, 256>>>(out);
}

// round 17
// speedup vs baseline: 1.7962x; 1.0121x over previous
#include <cuda_runtime.h>
#include <cuda_fp16.h>
#include <cstdint>

#define NN 50000
#define NE 600000
#define DD 128
#define NC 64
#define SWIDE 136   // padded row stride in fp16 elems (272B) -> conflict-free ldmatrix

// ---------------- scratch (no allocations allowed) ----------------
// counters are zero at module load and re-zeroed at the END of scatter_kernel,
// so every kernel_launch call sees them zeroed (replay-invariant).
__device__ float g_xw[NN * DD];
__device__ int   g_deg[NN];
__device__ float g_dinv[NN];
__device__ int   g_cluster_edges[NC];
__device__ int   g_intra_src[NE];
__device__ int   g_intra_dst[NE];
__device__ int   g_intra_count;
__device__ int   g_scatter_cnt;     // snapshot taken by gemm (block 0)
__device__ int   g_is_src[NN];
__device__ __align__(16) __half g_wt[DD * SWIDE];

__device__ __forceinline__ uint32_t packh2(__half a, __half b) {
    __half2 t = __halves2half2(a, b);
    return *reinterpret_cast<uint32_t*>(&t);
}
__device__ __forceinline__ void mma16816(float c[4], const uint32_t a[4],
                                         uint32_t b0, uint32_t b1) {
    asm volatile(
        "mma.sync.aligned.m16n8k16.row.col.f32.f16.f16.f32 "
        "{%0,%1,%2,%3}, {%4,%5,%6,%7}, {%8,%9}, {%0,%1,%2,%3};"
        : "+f"(c[0]), "+f"(c[1]), "+f"(c[2]), "+f"(c[3])
        : "r"(a[0]), "r"(a[1]), "r"(a[2]), "r"(a[3]), "r"(b0), "r"(b1));
}
__device__ __forceinline__ void ldsm_x4(uint32_t r[4], uint32_t saddr) {
    asm volatile(
        "ldmatrix.sync.aligned.m8n8.x4.shared.b16 {%0,%1,%2,%3}, [%4];"
        : "=r"(r[0]), "=r"(r[1]), "=r"(r[2]), "=r"(r[3]) : "r"(saddr));
}
__device__ __forceinline__ uint32_t smem_to_u32(const void* p) {
    uint32_t a;
    asm("{ .reg .u64 t; cvta.to.shared.u64 t, %1; cvt.u32.u64 %0, t; }"
        : "=r"(a) : "l"(p));
    return a;
}
__device__ __forceinline__ void cp_async16(uint32_t saddr, const void* gptr) {
    asm volatile("cp.async.cg.shared.global [%0], [%1], 16;"
                 :: "r"(saddr), "l"(gptr));
}

// ---------------- kernel 1: edge pass (4 edges/thread) + W prep -------------
// edge blocks: each thread handles 4 edges (2x int4 load, 8 parallel cl gathers),
// warp-scan aggregated compaction (1 atomic per warp for up to 128 edges).
__global__ void edge_wprep_kernel(const int* __restrict__ ei,
                                  const int* __restrict__ cl,
                                  const float* __restrict__ W,
                                  int E, int edge_blocks) {
    if ((int)blockIdx.x >= edge_blocks) {
        int i = ((int)blockIdx.x - edge_blocks) * 256 + threadIdx.x;
        if (i < DD * SWIDE) {
            int nrow = i / SWIDE;
            int k    = i % SWIDE;
            g_wt[i] = (k < DD) ? __float2half_rn(W[k * DD + nrow])
                               : __float2half_rn(0.f);
        }
        return;
    }
    const int t  = blockIdx.x * blockDim.x + threadIdx.x;
    const int e0 = t * 4;
    const int lane = threadIdx.x & 31;

    int s[4], d[4], cs[4];
    bool intra[4] = {false, false, false, false};
    if (e0 + 3 < E) {
        int4 sv = *(const int4*)(ei + e0);
        int4 dv = *(const int4*)(ei + E + e0);
        s[0] = sv.x; s[1] = sv.y; s[2] = sv.z; s[3] = sv.w;
        d[0] = dv.x; d[1] = dv.y; d[2] = dv.z; d[3] = dv.w;
        int cd[4];
        #pragma unroll
        for (int j = 0; j < 4; j++) cs[j] = cl[s[j]];
        #pragma unroll
        for (int j = 0; j < 4; j++) cd[j] = cl[d[j]];
        #pragma unroll
        for (int j = 0; j < 4; j++) intra[j] = (cs[j] == cd[j]);
    } else {
        #pragma unroll
        for (int j = 0; j < 4; j++) {
            int e = e0 + j;
            if (e < E) {
                s[j] = ei[e];
                d[j] = ei[E + e];
                cs[j] = cl[s[j]];
                intra[j] = (cs[j] == cl[d[j]]);
            }
        }
    }

    unsigned cnt = (unsigned)intra[0] + intra[1] + intra[2] + intra[3];
    // warp inclusive scan of cnt
    unsigned pre = cnt;
    #pragma unroll
    for (int o = 1; o < 32; o <<= 1) {
        unsigned v = __shfl_up_sync(0xFFFFFFFFu, pre, o);
        if (lane >= o) pre += v;
    }
    unsigned tot = __shfl_sync(0xFFFFFFFFu, pre, 31);
    int base = 0;
    if (tot > 0) {
        if (lane == 31) base = atomicAdd(&g_intra_count, (int)tot);
        base = __shfl_sync(0xFFFFFFFFu, base, 31);
        int p = base + (int)(pre - cnt);
        #pragma unroll
        for (int j = 0; j < 4; j++) {
            if (intra[j]) {
                atomicAdd(&g_deg[d[j]], 1);
                atomicAdd(&g_cluster_edges[cs[j]], 1);
                g_is_src[s[j]] = 1;
                g_intra_src[p] = s[j];
                g_intra_dst[p] = d[j];
                p++;
            }
        }
    }
}

// ---------------- kernel 2: fused fp16 2-term HMMA GEMM + node epilogue -----
#define ATILE (64 * SWIDE * 2)          // 17408 B
#define WTILE (DD * SWIDE * 2)          // 34816 B
#define SM_B    0
#define SM_AHI  512
#define SM_ALO  (512 + ATILE)
#define SM_W    (512 + 2 * ATILE)
#define SM_TOT  (512 + 2 * ATILE + WTILE)   // 70144 B -> 2 CTAs/SM

__global__ void __launch_bounds__(256, 2)
gemm_fused_kernel(const float* __restrict__ X,
                  const float* __restrict__ b,
                  const int* __restrict__ cl,
                  float* __restrict__ out,
                  int n) {
    extern __shared__ char smem[];
    float* bias = (float*)(smem + SM_B);
    __half* Ahi = (__half*)(smem + SM_AHI);
    __half* Alo = (__half*)(smem + SM_ALO);

    const int tid  = threadIdx.x;
    const int row0 = blockIdx.x * 64;
    const uint32_t sbase = smem_to_u32(smem);

    if (blockIdx.x == 0 && tid == 0) g_scatter_cnt = g_intra_count;

    // async W copy overlapping the X prologue
    {
        const uint4* gw = (const uint4*)g_wt;
        #pragma unroll
        for (int i = tid; i < 2176; i += 256)
            cp_async16(sbase + SM_W + i * 16, gw + i);
        asm volatile("cp.async.commit_group;");
    }

    if (tid < 128) bias[tid] = b[tid];

    // load X tile (64 rows), fp16 split, store padded
    {
        const float4* X4 = (const float4*)X;
        #pragma unroll
        for (int i = tid; i < 64 * 16; i += 256) {
            int row = i >> 4;
            int c   = i & 15;
            int grow = row0 + row;
            float4 a = make_float4(0.f, 0.f, 0.f, 0.f), a2 = a;
            if (grow < n) {
                a  = X4[grow * 32 + c * 2];
                a2 = X4[grow * 32 + c * 2 + 1];
            }
            float v[8] = {a.x, a.y, a.z, a.w, a2.x, a2.y, a2.z, a2.w};
            uint32_t hi[4], lo[4];
            #pragma unroll
            for (int j = 0; j < 4; j++) {
                __half h0 = __float2half_rn(v[2 * j]);
                __half h1 = __float2half_rn(v[2 * j + 1]);
                __half l0 = __float2half_rn(v[2 * j]     - __half2float(h0));
                __half l1 = __float2half_rn(v[2 * j + 1] - __half2float(h1));
                hi[j] = packh2(h0, h1);
                lo[j] = packh2(l0, l1);
            }
            *(uint4*)(Ahi + row * SWIDE + c * 8) = make_uint4(hi[0], hi[1], hi[2], hi[3]);
            *(uint4*)(Alo + row * SWIDE + c * 8) = make_uint4(lo[0], lo[1], lo[2], lo[3]);
        }
    }
    asm volatile("cp.async.wait_group 0;" ::: "memory");
    __syncthreads();

    const int wid  = tid >> 5;
    const int lane = tid & 31;
    const int mw   = wid >> 2;
    const int nwp  = wid & 3;
    const int g    = lane >> 2;
    const int tg   = lane & 3;

    const uint32_t aoff =
        ((uint32_t)(mw * 32 + (lane & 15)) * SWIDE + (uint32_t)(lane >> 4) * 8) * 2;
    const uint32_t boff =
        ((uint32_t)(nwp * 32 + ((lane >> 4) & 1) * 8 + (lane & 7)) * SWIDE
         + (uint32_t)((lane >> 3) & 1) * 8) * 2;
    const uint32_t AhiB = sbase + SM_AHI + aoff;
    const uint32_t AloB = sbase + SM_ALO + aoff;
    const uint32_t WB   = sbase + SM_W + boff;
    const uint32_t STEP16 = 16u * SWIDE * 2u;

    float acc[2][4][4];
    #pragma unroll
    for (int mt = 0; mt < 2; mt++)
        #pragma unroll
        for (int nt = 0; nt < 4; nt++)
            #pragma unroll
            for (int j = 0; j < 4; j++) acc[mt][nt][j] = 0.f;

    uint32_t b01[4], b23[4], ah0[4], ah1[4], al0[4], al1[4];
    ldsm_x4(b01, WB);
    ldsm_x4(b23, WB + STEP16);
    ldsm_x4(ah0, AhiB);
    ldsm_x4(ah1, AhiB + STEP16);
    ldsm_x4(al0, AloB);
    ldsm_x4(al1, AloB + STEP16);
    #pragma unroll
    for (int ks = 0; ks < 8; ks++) {
        uint32_t nb01[4], nb23[4], nah0[4], nah1[4], nal0[4], nal1[4];
        if (ks < 7) {
            const uint32_t ko = (uint32_t)(ks + 1) * 32u;
            ldsm_x4(nb01, WB + ko);
            ldsm_x4(nb23, WB + ko + STEP16);
            ldsm_x4(nah0, AhiB + ko);
            ldsm_x4(nah1, AhiB + ko + STEP16);
            ldsm_x4(nal0, AloB + ko);
            ldsm_x4(nal1, AloB + ko + STEP16);
        }
        mma16816(acc[0][0], ah0, b01[0], b01[1]);
        mma16816(acc[0][1], ah0, b01[2], b01[3]);
        mma16816(acc[0][2], ah0, b23[0], b23[1]);
        mma16816(acc[0][3], ah0, b23[2], b23[3]);
        mma16816(acc[1][0], ah1, b01[0], b01[1]);
        mma16816(acc[1][1], ah1, b01[2], b01[3]);
        mma16816(acc[1][2], ah1, b23[0], b23[1]);
        mma16816(acc[1][3], ah1, b23[2], b23[3]);
        mma16816(acc[0][0], al0, b01[0], b01[1]);
        mma16816(acc[0][1], al0, b01[2], b01[3]);
        mma16816(acc[0][2], al0, b23[0], b23[1]);
        mma16816(acc[0][3], al0, b23[2], b23[3]);
        mma16816(acc[1][0], al1, b01[0], b01[1]);
        mma16816(acc[1][1], al1, b01[2], b01[3]);
        mma16816(acc[1][2], al1, b23[0], b23[1]);
        mma16816(acc[1][3], al1, b23[2], b23[3]);
        if (ks < 7) {
            #pragma unroll
            for (int j = 0; j < 4; j++) {
                b01[j] = nb01[j]; b23[j] = nb23[j];
                ah0[j] = nah0[j]; ah1[j] = nah1[j];
                al0[j] = nal0[j]; al1[j] = nal1[j];
            }
        }
    }

    if (tid < 64) {
        int row = row0 + tid;
        if (row < n) g_dinv[row] = rsqrtf((float)g_deg[row] + 1.0f);
    }

    #pragma unroll
    for (int mt = 0; mt < 2; mt++) {
        #pragma unroll
        for (int half = 0; half < 2; half++) {
            int row = row0 + mw * 32 + mt * 16 + g + half * 8;
            if (row >= n) continue;
            float deg = (float)g_deg[row] + 1.0f;
            float inv = 1.0f / deg;
            bool  has = (g_cluster_edges[cl[row]] > 0);
            bool  src = (g_is_src[row] != 0);
            #pragma unroll
            for (int nt = 0; nt < 4; nt++) {
                int ncol = nwp * 32 + nt * 8 + tg * 2;
                float2 v = make_float2(acc[mt][nt][half * 2],
                                       acc[mt][nt][half * 2 + 1]);
                if (src) *(float2*)(g_xw + row * DD + ncol) = v;
                float2 o;
                if (has) {
                    o.x = fmaf(v.x, inv, bias[ncol]);
                    o.y = fmaf(v.y, inv, bias[ncol + 1]);
                } else {
                    o = *(const float2*)(X + row * DD + ncol);
                }
                *(float2*)(out + row * DD + ncol) = o;
            }
        }
    }
}

// ---------------- kernel 3: scatter + counter cleanup for next replay -------
__global__ void scatter_kernel(float* __restrict__ out) {
    int cnt  = g_scatter_cnt;
    int gtid = blockIdx.x * blockDim.x + threadIdx.x;
    int nthr = gridDim.x * blockDim.x;
    int warp = gtid >> 5;
    int lane = gtid & 31;
    int nw   = nthr >> 5;

    for (int e = warp; e < cnt; e += nw) {
        int s = g_intra_src[e];
        int d = g_intra_dst[e];
        float w = g_dinv[s] * g_dinv[d];
        float4 v = ((const float4*)(g_xw + s * DD))[lane];
        float* o = out + d * DD + lane * 4;
        atomicAdd(o + 0, w * v.x);
        atomicAdd(o + 1, w * v.y);
        atomicAdd(o + 2, w * v.z);
        atomicAdd(o + 3, w * v.w);
    }

    for (int i = gtid; i < NN; i += nthr) { g_deg[i] = 0; g_is_src[i] = 0; }
    if (gtid < NC) g_cluster_edges[gtid] = 0;
    if (gtid == 0) g_intra_count = 0;
}

// ---------------- launch ----------------
extern "C" void kernel_launch(void* const* d_in, const int* in_sizes, int n_in,
                              void* d_out, int out_size) {
    const float* X  = (const float*)d_in[0];
    const float* W  = (const float*)d_in[1];
    const float* b  = (const float*)d_in[2];
    // d_in[3] = edge_attr (unused)
    const int* cl = (const int*)d_in[4];
    const int* ei = (const int*)d_in[5];
    float* out = (float*)d_out;

    const int N = in_sizes[4];
    const int E = in_sizes[3];

    cudaFuncSetAttribute(gemm_fused_kernel,
                         cudaFuncAttributeMaxDynamicSharedMemorySize, SM_TOT);

    const int edge_threads = (E + 3) / 4;
    const int edge_blocks  = (edge_threads + 255) / 256;
    const int wprep_blocks = (DD * SWIDE + 255) / 256;
    edge_wprep_kernel<<<edge_blocks + wprep_blocks, 256>>>(ei, cl, W, E, edge_blocks);
    gemm_fused_kernel<<<(N + 63) / 64, 256, SM_TOT>>>(X, b, cl, out, N);
    scatter_kernel<<<512, 256>>>(out);
}